// round 1
// baseline (speedup 1.0000x reference)
#include <cuda_runtime.h>
#include <cuda_bf16.h>
#include <math.h>

// Problem constants (fixed by the dataset)
#define T_TOK 512
#define HDIM 2880
#define IDIM 2880
#define TWO_I 5760
#define NEXP 8
#define KSEL 4

#define ALPHA 1.702f
#define LIMIT 7.0f

// ---------------- device scratch (no allocations allowed) ----------------
__device__ int   g_cnt[NEXP];                 // tokens routed to each expert
__device__ int   g_tok[NEXP * T_TOK];         // gathered token index per (e, local)
__device__ float g_wt [NEXP * T_TOK];         // combine weight per (e, local)
__device__ int   g_nslots[T_TOK];             // distinct experts per token
__device__ int   g_slots[T_TOK * KSEL];       // slot = e*T + local, per token
__device__ float g_h[(size_t)NEXP * T_TOK * IDIM];  // GEMM1 activated output (47MB)
__device__ float g_o[(size_t)NEXP * T_TOK * HDIM];  // GEMM2 scaled output   (47MB)

// ---------------- kernel 0: zero counters ----------------
__global__ void zero_kernel() {
    int i = threadIdx.x;
    if (i < NEXP) g_cnt[i] = 0;
}

// ---------------- kernel 1: build routing lists ----------------
__global__ void build_kernel(const int* __restrict__ ridx,
                             const float* __restrict__ rw) {
    int t = blockIdx.x * blockDim.x + threadIdx.x;
    if (t >= T_TOK) return;
    int id[KSEL];
#pragma unroll
    for (int k = 0; k < KSEL; k++) id[k] = ridx[t * KSEL + k];
    int ns = 0;
#pragma unroll
    for (int k = 0; k < KSEL; k++) {
        bool first = true;
#pragma unroll
        for (int j = 0; j < KSEL; j++)
            if (j < k && id[j] == id[k]) first = false;
        if (!first) continue;
        int c = 0;
#pragma unroll
        for (int j = 0; j < KSEL; j++)
            if (id[j] == id[k]) c++;
        int e = id[k];
        float w = rw[t * NEXP + e] * (float)c;
        int loc = atomicAdd(&g_cnt[e], 1);
        g_tok[e * T_TOK + loc] = t;
        g_wt [e * T_TOK + loc] = w;
        g_slots[t * KSEL + ns] = e * T_TOK + loc;
        ns++;
    }
    g_nslots[t] = ns;
}

// ---------------- kernel 2: GEMM1 + clamped-GLU ----------------
// Per expert e: A = gathered x rows [cnt, H]; B = gate_up_proj[e] [H, 2I].
// Output pair p -> gate col 2p, up col 2p+1. Block tile: 128 rows x 64 pairs.
// 256 threads, each computes 8 rows x 4 pairs (gate+up accumulators).
#define BK 16
__global__ __launch_bounds__(256)
void gemm1_kernel(const float* __restrict__ x,
                  const float* __restrict__ w1,
                  const float* __restrict__ b1) {
    int e   = blockIdx.z;
    int cnt = g_cnt[e];
    int m0  = blockIdx.y * 128;
    if (m0 >= cnt) return;
    int n0p = blockIdx.x * 64;  // pair offset

    __shared__ float As[BK][128];
    __shared__ float Bs[BK][128];

    int tid = threadIdx.x;
    int tx = tid & 15, ty = tid >> 4;

    // A-load mapping: row = tid/2, two float4 along K
    int ar  = tid >> 1;
    int akq = (tid & 1) * 8;   // k offset within tile (0 or 8)
    int gm  = m0 + ar;
    int arow_tok = (gm < cnt) ? g_tok[e * T_TOK + gm] : -1;

    // B-load mapping: k-row = tid/16, 8 consecutive cols at (tid%16)*8
    int bkr = tid >> 4;
    int bcg = tid & 15;
    const float* w1e = w1 + (size_t)e * HDIM * TWO_I;

    float accg[8][4], accu[8][4];
#pragma unroll
    for (int i = 0; i < 8; i++)
#pragma unroll
        for (int j = 0; j < 4; j++) { accg[i][j] = 0.f; accu[i][j] = 0.f; }

    for (int k0 = 0; k0 < HDIM; k0 += BK) {
        float4 a0 = make_float4(0.f, 0.f, 0.f, 0.f), a1 = a0;
        if (arow_tok >= 0) {
            const float* xp = x + (size_t)arow_tok * HDIM + k0 + akq;
            a0 = *(const float4*)xp;
            a1 = *(const float4*)(xp + 4);
        }
        As[akq + 0][ar] = a0.x; As[akq + 1][ar] = a0.y;
        As[akq + 2][ar] = a0.z; As[akq + 3][ar] = a0.w;
        As[akq + 4][ar] = a1.x; As[akq + 5][ar] = a1.y;
        As[akq + 6][ar] = a1.z; As[akq + 7][ar] = a1.w;

        const float* bp = w1e + (size_t)(k0 + bkr) * TWO_I + n0p * 2 + bcg * 8;
        *(float4*)&Bs[bkr][bcg * 8]     = *(const float4*)bp;
        *(float4*)&Bs[bkr][bcg * 8 + 4] = *(const float4*)(bp + 4);
        __syncthreads();

#pragma unroll
        for (int kk = 0; kk < BK; kk++) {
            float4 a0s = *(float4*)&As[kk][ty * 8];
            float4 a1s = *(float4*)&As[kk][ty * 8 + 4];
            float4 f0  = *(float4*)&Bs[kk][tx * 8];
            float4 f1  = *(float4*)&Bs[kk][tx * 8 + 4];
            float av[8] = {a0s.x, a0s.y, a0s.z, a0s.w, a1s.x, a1s.y, a1s.z, a1s.w};
            float gv[4] = {f0.x, f0.z, f1.x, f1.z};
            float uv[4] = {f0.y, f0.w, f1.y, f1.w};
#pragma unroll
            for (int i = 0; i < 8; i++)
#pragma unroll
                for (int j = 0; j < 4; j++) {
                    accg[i][j] += av[i] * gv[j];
                    accu[i][j] += av[i] * uv[j];
                }
        }
        __syncthreads();
    }

    // biases for this thread's 4 pairs
    const float* bb = b1 + (size_t)e * TWO_I + n0p * 2 + tx * 8;
    float4 bg0 = *(const float4*)bb;
    float4 bg1 = *(const float4*)(bb + 4);
    float biasg[4] = {bg0.x, bg0.z, bg1.x, bg1.z};
    float biasu[4] = {bg0.y, bg0.w, bg1.y, bg1.w};

#pragma unroll
    for (int i = 0; i < 8; i++) {
        int m = m0 + ty * 8 + i;
        if (m >= cnt) continue;
        float hv[4];
#pragma unroll
        for (int j = 0; j < 4; j++) {
            float gate = fminf(accg[i][j] + biasg[j], LIMIT);
            float up   = fminf(fmaxf(accu[i][j] + biasu[j], -LIMIT), LIMIT);
            float glu  = gate / (1.0f + expf(-ALPHA * gate));
            hv[j] = (up + 1.0f) * glu;
        }
        float4 v = make_float4(hv[0], hv[1], hv[2], hv[3]);
        *(float4*)&g_h[((size_t)e * T_TOK + m) * IDIM + n0p + tx * 4] = v;
    }
}

// ---------------- kernel 3: GEMM2 + bias + combine-weight ----------------
// A = g_h[e] rows [cnt, I]; B = down_proj[e] [I, H]. Tile 128 x 64.
__global__ __launch_bounds__(256)
void gemm2_kernel(const float* __restrict__ w2,
                  const float* __restrict__ b2) {
    int e   = blockIdx.z;
    int cnt = g_cnt[e];
    int m0  = blockIdx.y * 128;
    if (m0 >= cnt) return;
    int n0 = blockIdx.x * 64;

    __shared__ float As[BK][128];
    __shared__ float Bs[BK][64];

    int tid = threadIdx.x;
    int tx = tid & 15, ty = tid >> 4;

    int ar  = tid >> 1;
    int akq = (tid & 1) * 8;
    int gm  = m0 + ar;
    bool avalid = (gm < cnt);
    const float* ap_base = &g_h[((size_t)e * T_TOK + gm) * IDIM];

    int bkr = tid >> 4;
    int bcg = tid & 15;
    const float* w2e = w2 + (size_t)e * IDIM * HDIM;

    float acc[8][4];
#pragma unroll
    for (int i = 0; i < 8; i++)
#pragma unroll
        for (int j = 0; j < 4; j++) acc[i][j] = 0.f;

    for (int k0 = 0; k0 < IDIM; k0 += BK) {
        float4 a0 = make_float4(0.f, 0.f, 0.f, 0.f), a1 = a0;
        if (avalid) {
            const float* ap = ap_base + k0 + akq;
            a0 = *(const float4*)ap;
            a1 = *(const float4*)(ap + 4);
        }
        As[akq + 0][ar] = a0.x; As[akq + 1][ar] = a0.y;
        As[akq + 2][ar] = a0.z; As[akq + 3][ar] = a0.w;
        As[akq + 4][ar] = a1.x; As[akq + 5][ar] = a1.y;
        As[akq + 6][ar] = a1.z; As[akq + 7][ar] = a1.w;

        const float* bp = w2e + (size_t)(k0 + bkr) * HDIM + n0 + bcg * 4;
        *(float4*)&Bs[bkr][bcg * 4] = *(const float4*)bp;
        __syncthreads();

#pragma unroll
        for (int kk = 0; kk < BK; kk++) {
            float4 a0s = *(float4*)&As[kk][ty * 8];
            float4 a1s = *(float4*)&As[kk][ty * 8 + 4];
            float4 b   = *(float4*)&Bs[kk][tx * 4];
            float av[8] = {a0s.x, a0s.y, a0s.z, a0s.w, a1s.x, a1s.y, a1s.z, a1s.w};
            float bv[4] = {b.x, b.y, b.z, b.w};
#pragma unroll
            for (int i = 0; i < 8; i++)
#pragma unroll
                for (int j = 0; j < 4; j++)
                    acc[i][j] += av[i] * bv[j];
        }
        __syncthreads();
    }

    float4 bias = *(const float4*)(b2 + (size_t)e * HDIM + n0 + tx * 4);
    float bv[4] = {bias.x, bias.y, bias.z, bias.w};

#pragma unroll
    for (int i = 0; i < 8; i++) {
        int m = m0 + ty * 8 + i;
        if (m >= cnt) continue;
        float w = g_wt[e * T_TOK + m];
        float4 v = make_float4(w * (acc[i][0] + bv[0]),
                               w * (acc[i][1] + bv[1]),
                               w * (acc[i][2] + bv[2]),
                               w * (acc[i][3] + bv[3]));
        *(float4*)&g_o[((size_t)e * T_TOK + m) * HDIM + n0 + tx * 4] = v;
    }
}

// ---------------- kernel 4: deterministic per-token combine ----------------
__global__ void combine_kernel(float* __restrict__ out) {
    int t = blockIdx.x;
    int ns = g_nslots[t];
    int sl[KSEL];
#pragma unroll
    for (int j = 0; j < KSEL; j++)
        sl[j] = (j < ns) ? g_slots[t * KSEL + j] : -1;

    for (int c = threadIdx.x * 4; c < HDIM; c += blockDim.x * 4) {
        float4 acc = make_float4(0.f, 0.f, 0.f, 0.f);
#pragma unroll
        for (int j = 0; j < KSEL; j++) {
            if (sl[j] < 0) continue;
            float4 v = *(const float4*)&g_o[(size_t)sl[j] * HDIM + c];
            acc.x += v.x; acc.y += v.y; acc.z += v.z; acc.w += v.w;
        }
        *(float4*)&out[(size_t)t * HDIM + c] = acc;
    }
}

// ---------------- launch ----------------
extern "C" void kernel_launch(void* const* d_in, const int* in_sizes, int n_in,
                              void* d_out, int out_size) {
    const float* x    = (const float*)d_in[0];  // hidden_states [1,512,2880]
    const int*   ridx = (const int*)  d_in[1];  // router_indices [512,4]
    const float* rw   = (const float*)d_in[2];  // routing_weights [512,8]
    const float* w1   = (const float*)d_in[3];  // gate_up_proj [8,2880,5760]
    const float* b1   = (const float*)d_in[4];  // gate_up_proj_bias [8,5760]
    const float* w2   = (const float*)d_in[5];  // down_proj [8,2880,2880]
    const float* b2   = (const float*)d_in[6];  // down_proj_bias [8,2880]
    float* out = (float*)d_out;

    zero_kernel<<<1, 32>>>();
    build_kernel<<<2, 256>>>(ridx, rw);

    dim3 g1(TWO_I / 128, (T_TOK + 127) / 128, NEXP);   // (45, 4, 8)
    gemm1_kernel<<<g1, 256>>>(x, w1, b1);

    dim3 g2(HDIM / 64, (T_TOK + 127) / 128, NEXP);     // (45, 4, 8)
    gemm2_kernel<<<g2, 256>>>(w2, b2);

    combine_kernel<<<T_TOK, 256>>>(out);
}

// round 4
// speedup vs baseline: 2.2201x; 2.2201x over previous
#include <cuda_runtime.h>
#include <cuda_bf16.h>
#include <cstdint>
#include <math.h>

// ---------------- problem constants ----------------
#define T_TOK 512
#define HDIM 2880
#define IDIM 2880
#define TWO_I 5760
#define NEXP 8
#define KSEL 4
#define ALPHA 1.702f
#define LIMIT 7.0f

// ---------------- GEMM tiling ----------------
#define MT 128
#define NT 64
#define KC 32
#define NCHUNK (HDIM / KC)     // 90
#define ROWSTR 40              // smem row stride in bf16 elems (32 data + 8 pad)

#define SA_ELEMS (MT * ROWSTR)                 // 5120
#define SB_ELEMS (NT * ROWSTR)                 // 2560
#define STAGE_ELEMS (2 * SA_ELEMS + 2 * SB_ELEMS)  // 15360 elems = 30720 B
#define SMEM_BYTES (2 * STAGE_ELEMS * 2)           // 61440 B

// ---------------- device scratch ----------------
__device__ int   g_cnt[NEXP];
__device__ int   g_tok[NEXP * T_TOK];
__device__ float g_wt [NEXP * T_TOK];
__device__ int   g_nslots[T_TOK];
__device__ int   g_slots[T_TOK * KSEL];
__device__ float g_h[(size_t)NEXP * T_TOK * IDIM];
__device__ float g_o[(size_t)NEXP * T_TOK * HDIM];

// ---------------- helpers ----------------
__device__ __forceinline__ uint32_t smem_u32(const void* p) {
    uint32_t a;
    asm("{ .reg .u64 t; cvta.to.shared.u64 t, %1; cvt.u32.u64 %0, t; }" : "=r"(a) : "l"(p));
    return a;
}

__device__ __forceinline__ void mma_bf16(float* c, const uint32_t* a, const uint32_t* b) {
    asm volatile(
        "mma.sync.aligned.m16n8k16.row.col.f32.bf16.bf16.f32 "
        "{%0,%1,%2,%3}, {%4,%5,%6,%7}, {%8,%9}, {%0,%1,%2,%3};"
        : "+f"(c[0]), "+f"(c[1]), "+f"(c[2]), "+f"(c[3])
        : "r"(a[0]), "r"(a[1]), "r"(a[2]), "r"(a[3]), "r"(b[0]), "r"(b[1]));
}

__device__ __forceinline__ void ldm_x4(uint32_t* r, uint32_t addr) {
    asm volatile("ldmatrix.sync.aligned.m8n8.x4.shared.b16 {%0,%1,%2,%3}, [%4];"
                 : "=r"(r[0]), "=r"(r[1]), "=r"(r[2]), "=r"(r[3]) : "r"(addr));
}

// fp32[8] -> bf16 hi/lo packed uint4 pair
union U8 { unsigned short s[8]; uint4 q; };
__device__ __forceinline__ void cvt8(const float* v, uint4& hiq, uint4& loq) {
    U8 h, l;
#pragma unroll
    for (int i = 0; i < 8; i++) {
        __nv_bfloat16 bh = __float2bfloat16(v[i]);
        float r = v[i] - __bfloat162float(bh);
        __nv_bfloat16 bl = __float2bfloat16(r);
        h.s[i] = *(unsigned short*)&bh;
        l.s[i] = *(unsigned short*)&bl;
    }
    hiq = h.q; loq = l.q;
}

// ---------------- routing kernels ----------------
__global__ void zero_kernel() {
    int i = threadIdx.x;
    if (i < NEXP) g_cnt[i] = 0;
}
__global__ void build_kernel(const int* __restrict__ ridx,
                             const float* __restrict__ rw) {
    int t = blockIdx.x * blockDim.x + threadIdx.x;
    if (t >= T_TOK) return;
    int id[KSEL];
#pragma unroll
    for (int k = 0; k < KSEL; k++) id[k] = ridx[t * KSEL + k];
    int ns = 0;
#pragma unroll
    for (int k = 0; k < KSEL; k++) {
        bool first = true;
#pragma unroll
        for (int j = 0; j < KSEL; j++)
            if (j < k && id[j] == id[k]) first = false;
        if (!first) continue;
        int c = 0;
#pragma unroll
        for (int j = 0; j < KSEL; j++)
            if (id[j] == id[k]) c++;
        int e = id[k];
        float w = rw[t * NEXP + e] * (float)c;
        int loc = atomicAdd(&g_cnt[e], 1);
        g_tok[e * T_TOK + loc] = t;
        g_wt [e * T_TOK + loc] = w;
        g_slots[t * KSEL + ns] = e * T_TOK + loc;
        ns++;
    }
    g_nslots[t] = ns;
}

// ---------------- mma.sync GEMM: MODE 0 = gate_up+GLU, MODE 1 = down+scale ----------------
template <int MODE>
__global__ __launch_bounds__(256, 2)
void moe_mma_kernel(const float* __restrict__ x,
                    const float* __restrict__ Bw,
                    const float* __restrict__ bias) {
    constexpr int LDB = (MODE == 0) ? TWO_I : HDIM;
    extern __shared__ __nv_bfloat16 smem[];

    int e   = blockIdx.z;
    int cnt = g_cnt[e];
    int m0  = blockIdx.y * MT;
    if (m0 >= cnt) return;
    int n0  = blockIdx.x * NT;

    int tid  = threadIdx.x;
    int lane = tid & 31, wid = tid >> 5;
    int wm = wid >> 1, wn = wid & 1;   // warp tile: rows [wm*32,+32), cols [wn*32,+32)

    // ---- A prefetch mapping: row = tid/2, 16 consecutive k at (tid&1)*16 ----
    int arow_i = tid >> 1;
    int akh    = (tid & 1) * 16;
    const float* arow = nullptr;
    if (m0 + arow_i < cnt) {
        if (MODE == 0) arow = x   + (size_t)g_tok[e * T_TOK + m0 + arow_i] * HDIM;
        else           arow = g_h + ((size_t)e * T_TOK + m0 + arow_i) * IDIM;
    }
    // ---- B prefetch mapping: col n = tid&63, 8 k rows at (tid>>6)*8 ----
    const float* Be = Bw + (size_t)e * HDIM * LDB + n0;
    int bn  = tid & 63;
    int bkq = (tid >> 6) * 8;

    uint32_t sb = smem_u32(smem);

    float av[16], bv[8];

    auto loadA = [&](int c) {
        if (arow) {
            const float* p = arow + c * KC + akh;
#pragma unroll
            for (int i = 0; i < 4; i++) {
                float4 v = *(const float4*)(p + i * 4);
                av[i*4+0] = v.x; av[i*4+1] = v.y; av[i*4+2] = v.z; av[i*4+3] = v.w;
            }
        } else {
#pragma unroll
            for (int i = 0; i < 16; i++) av[i] = 0.f;
        }
    };
    auto loadB = [&](int c) {
        const float* p = Be + (size_t)(c * KC + bkq) * LDB + bn;
#pragma unroll
        for (int j = 0; j < 8; j++) bv[j] = p[(size_t)j * LDB];
    };
    auto storeStage = [&](int s) {
        __nv_bfloat16* base = smem + s * STAGE_ELEMS;
        uint4 h0, l0, h1, l1;
        cvt8(av, h0, l0); cvt8(av + 8, h1, l1);
        __nv_bfloat16* pa = base + arow_i * ROWSTR + akh;
        *(uint4*)(pa)                 = h0;
        *(uint4*)(pa + 8)             = h1;
        *(uint4*)(pa + SA_ELEMS)      = l0;
        *(uint4*)(pa + SA_ELEMS + 8)  = l1;
        uint4 bh, bl;
        cvt8(bv, bh, bl);
        __nv_bfloat16* pb = base + 2 * SA_ELEMS + bn * ROWSTR + bkq;
        *(uint4*)(pb)             = bh;
        *(uint4*)(pb + SB_ELEMS)  = bl;
    };

    float acc[2][4][4];
#pragma unroll
    for (int mi = 0; mi < 2; mi++)
#pragma unroll
        for (int ni = 0; ni < 4; ni++)
#pragma unroll
            for (int u = 0; u < 4; u++) acc[mi][ni][u] = 0.f;

    // ldmatrix lane-constant offsets (bf16 elements)
    int a_lo = ((lane & 7) + ((lane >> 3) & 1) * 8) * ROWSTR + ((lane >> 4) & 1) * 8;
    int b_lo = ((lane & 7) + ((lane >> 4) & 1) * 8) * ROWSTR + ((lane >> 3) & 1) * 8;

    loadA(0); loadB(0);
    storeStage(0);
    __syncthreads();

#pragma unroll 1
    for (int c = 0; c < NCHUNK; c++) {
        int cur = c & 1;
        bool more = (c + 1 < NCHUNK);
        if (more) { loadA(c + 1); loadB(c + 1); }

        uint32_t sAh = sb + (cur * STAGE_ELEMS) * 2;
        uint32_t sAl = sAh + SA_ELEMS * 2;
        uint32_t sBh = sAh + 2 * SA_ELEMS * 2;
        uint32_t sBl = sBh + SB_ELEMS * 2;

#pragma unroll
        for (int ks = 0; ks < 2; ks++) {
            uint32_t ah[2][4], al[2][4], bh[2][4], bl[2][4];
#pragma unroll
            for (int mi = 0; mi < 2; mi++) {
                uint32_t off = ((wm * 32 + mi * 16) * ROWSTR + ks * 16 + a_lo) * 2;
                ldm_x4(ah[mi], sAh + off);
                ldm_x4(al[mi], sAl + off);
            }
#pragma unroll
            for (int nh = 0; nh < 2; nh++) {
                uint32_t off = ((wn * 32 + nh * 16) * ROWSTR + ks * 16 + b_lo) * 2;
                ldm_x4(bh[nh], sBh + off);
                ldm_x4(bl[nh], sBl + off);
            }
#pragma unroll
            for (int mi = 0; mi < 2; mi++)
#pragma unroll
                for (int ni = 0; ni < 4; ni++) {
                    uint32_t* bhp = &bh[ni >> 1][(ni & 1) * 2];
                    uint32_t* blp = &bl[ni >> 1][(ni & 1) * 2];
                    mma_bf16(acc[mi][ni], ah[mi], bhp);
                    mma_bf16(acc[mi][ni], ah[mi], blp);
                    mma_bf16(acc[mi][ni], al[mi], bhp);
                }
        }

        if (more) storeStage(cur ^ 1);
        __syncthreads();
    }

    // ---- epilogue ----
    int r = lane >> 2, q = lane & 3;
#pragma unroll
    for (int mi = 0; mi < 2; mi++) {
        int mbase = m0 + wm * 32 + mi * 16 + r;
#pragma unroll
        for (int ni = 0; ni < 4; ni++) {
            int ncol = n0 + wn * 32 + ni * 8 + q * 2;
            if (MODE == 0) {
                float bg = bias[(size_t)e * TWO_I + ncol];
                float bu = bias[(size_t)e * TWO_I + ncol + 1];
                int hcol = ncol >> 1;
#pragma unroll
                for (int h2 = 0; h2 < 2; h2++) {
                    int m = mbase + h2 * 8;
                    if (m - m0 < MT && m < cnt) {
                        float gate = fminf(acc[mi][ni][h2 * 2 + 0] + bg, LIMIT);
                        float up   = fminf(fmaxf(acc[mi][ni][h2 * 2 + 1] + bu, -LIMIT), LIMIT);
                        float glu  = gate / (1.0f + expf(-ALPHA * gate));
                        g_h[((size_t)e * T_TOK + m) * IDIM + hcol] = (up + 1.0f) * glu;
                    }
                }
            } else {
                float b0v = bias[(size_t)e * HDIM + ncol];
                float b1v = bias[(size_t)e * HDIM + ncol + 1];
#pragma unroll
                for (int h2 = 0; h2 < 2; h2++) {
                    int m = mbase + h2 * 8;
                    if (m - m0 < MT && m < cnt) {
                        float w = g_wt[e * T_TOK + m];
                        float2 v;
                        v.x = (acc[mi][ni][h2 * 2 + 0] + b0v) * w;
                        v.y = (acc[mi][ni][h2 * 2 + 1] + b1v) * w;
                        *(float2*)&g_o[((size_t)e * T_TOK + m) * HDIM + ncol] = v;
                    }
                }
            }
        }
    }
}

// ---------------- deterministic per-token combine ----------------
__global__ void combine_kernel(float* __restrict__ out) {
    int t = blockIdx.x;
    int ns = g_nslots[t];
    int sl[KSEL];
#pragma unroll
    for (int j = 0; j < KSEL; j++)
        sl[j] = (j < ns) ? g_slots[t * KSEL + j] : -1;

    for (int c = threadIdx.x * 4; c < HDIM; c += blockDim.x * 4) {
        float4 acc = make_float4(0.f, 0.f, 0.f, 0.f);
#pragma unroll
        for (int j = 0; j < KSEL; j++) {
            if (sl[j] < 0) continue;
            float4 v = *(const float4*)&g_o[(size_t)sl[j] * HDIM + c];
            acc.x += v.x; acc.y += v.y; acc.z += v.z; acc.w += v.w;
        }
        *(float4*)&out[(size_t)t * HDIM + c] = acc;
    }
}

// ---------------- launch ----------------
extern "C" void kernel_launch(void* const* d_in, const int* in_sizes, int n_in,
                              void* d_out, int out_size) {
    const float* x    = (const float*)d_in[0];
    const int*   ridx = (const int*)  d_in[1];
    const float* rw   = (const float*)d_in[2];
    const float* w1   = (const float*)d_in[3];
    const float* b1   = (const float*)d_in[4];
    const float* w2   = (const float*)d_in[5];
    const float* b2   = (const float*)d_in[6];
    float* out = (float*)d_out;

    cudaFuncSetAttribute(moe_mma_kernel<0>,
                         cudaFuncAttributeMaxDynamicSharedMemorySize, SMEM_BYTES);
    cudaFuncSetAttribute(moe_mma_kernel<1>,
                         cudaFuncAttributeMaxDynamicSharedMemorySize, SMEM_BYTES);

    zero_kernel<<<1, 32>>>();
    build_kernel<<<2, 256>>>(ridx, rw);

    dim3 g1(TWO_I / NT, (T_TOK + MT - 1) / MT, NEXP);  // (90, 4, 8)
    moe_mma_kernel<0><<<g1, 256, SMEM_BYTES>>>(x, w1, b1);

    dim3 g2(HDIM / NT, (T_TOK + MT - 1) / MT, NEXP);   // (45, 4, 8)
    moe_mma_kernel<1><<<g2, 256, SMEM_BYTES>>>(x, w2, b2);

    combine_kernel<<<T_TOK, 256>>>(out);
}